// round 1
// baseline (speedup 1.0000x reference)
#include <cuda_runtime.h>
#include <cuda_bf16.h>
#include <math.h>

// ---------------- problem constants ----------------
#define N_PATCH 676          // 26*26
#define DIMV    384
#define M_LIB   100000
#define FMAP    26
#define IMG     224
#define KSIZE   33
#define KHALF   16

// ---------------- device scratch (no allocations allowed) ----------------
__device__ unsigned long long g_min[N_PATCH];       // packed (key<<32 | m_idx), min over bank
__device__ float              g_x2[N_PATCH];
__device__ float              g_y2[M_LIB];
__device__ float              g_minval[N_PATCH];    // min distance per patch
__device__ float              g_s_star;
__device__ int                g_sidx;
__device__ int                g_mstar;
__device__ unsigned long long g_wpack[M_LIB];       // packed w_dist keys
__device__ float              g_k1d[KSIZE];
__device__ float              g_up[IMG * IMG];
__device__ float              g_tmp[IMG * IMG];

// monotone float -> uint key (ascending float => ascending uint)
__device__ __forceinline__ unsigned int fenc(float f) {
    unsigned int u = __float_as_uint(f);
    return (u & 0x80000000u) ? ~u : (u | 0x80000000u);
}
__device__ __forceinline__ float fdec(unsigned int k) {
    unsigned int u = (k & 0x80000000u) ? (k ^ 0x80000000u) : ~k;
    return __uint_as_float(u);
}

// ---------------- init: reset mins + build gaussian kernel ----------------
__global__ void k_init() {
    int t = threadIdx.x;
    for (int i = t; i < N_PATCH; i += blockDim.x) g_min[i] = 0xFFFFFFFFFFFFFFFFull;
    if (t == 0) {
        double k[KSIZE]; double s = 0.0;
        for (int i = 0; i < KSIZE; i++) {
            double x = (double)i - (KSIZE - 1) / 2.0;
            k[i] = exp(-0.5 * (x / 4.0) * (x / 4.0));
            s += k[i];
        }
        for (int i = 0; i < KSIZE; i++) g_k1d[i] = (float)(k[i] / s);
    }
}

// ---------------- squared row norms (warp per row) ----------------
__global__ void k_sqnorm(const float* __restrict__ x, float* __restrict__ out, int rows) {
    int warp = (blockIdx.x * blockDim.x + threadIdx.x) >> 5;
    int lane = threadIdx.x & 31;
    if (warp >= rows) return;
    const float4* p = (const float4*)(x + (size_t)warp * DIMV);
    float s = 0.f;
    #pragma unroll 3
    for (int i = lane; i < DIMV / 4; i += 32) {
        float4 v = p[i];
        s += v.x * v.x + v.y * v.y + v.z * v.z + v.w * v.w;
    }
    #pragma unroll
    for (int o = 16; o; o >>= 1) s += __shfl_xor_sync(0xFFFFFFFFu, s, o);
    if (lane == 0) out[warp] = s;
}

// ---------------- fused GEMM + row-min:  score(n,m) = y2[m] - 2*dot(n,m) ----------------
// 64x64 tile, BK=16, 16x16 threads, 4x4 per-thread accumulators.
#define BK 16
__global__ __launch_bounds__(256) void k_gemm_min(const float* __restrict__ A,
                                                 const float* __restrict__ B) {
    __shared__ float As[BK][68];
    __shared__ float Bs[BK][68];
    __shared__ unsigned long long sMin[64][17];

    const int tx = threadIdx.x, ty = threadIdx.y;
    const int tid = ty * 16 + tx;
    const int n0 = blockIdx.y * 64;
    const int m0 = blockIdx.x * 64;

    const int lr = tid >> 2;         // 0..63  row within tile
    const int lc = (tid & 3) * 4;    // 0,4,8,12  k sub-offset

    float acc[4][4] = {};

    for (int k0 = 0; k0 < DIMV; k0 += BK) {
        float4 av = make_float4(0.f, 0.f, 0.f, 0.f);
        float4 bv = make_float4(0.f, 0.f, 0.f, 0.f);
        int an = n0 + lr;
        if (an < N_PATCH) av = *(const float4*)(A + (size_t)an * DIMV + k0 + lc);
        int bm = m0 + lr;
        if (bm < M_LIB)   bv = *(const float4*)(B + (size_t)bm * DIMV + k0 + lc);
        __syncthreads();
        As[lc + 0][lr] = av.x; As[lc + 1][lr] = av.y; As[lc + 2][lr] = av.z; As[lc + 3][lr] = av.w;
        Bs[lc + 0][lr] = bv.x; Bs[lc + 1][lr] = bv.y; Bs[lc + 2][lr] = bv.z; Bs[lc + 3][lr] = bv.w;
        __syncthreads();
        #pragma unroll
        for (int k = 0; k < BK; k++) {
            float4 a = *(const float4*)&As[k][ty * 4];
            float4 b = *(const float4*)&Bs[k][tx * 4];
            acc[0][0] += a.x * b.x; acc[0][1] += a.x * b.y; acc[0][2] += a.x * b.z; acc[0][3] += a.x * b.w;
            acc[1][0] += a.y * b.x; acc[1][1] += a.y * b.y; acc[1][2] += a.y * b.z; acc[1][3] += a.y * b.w;
            acc[2][0] += a.z * b.x; acc[2][1] += a.z * b.y; acc[2][2] += a.z * b.z; acc[2][3] += a.z * b.w;
            acc[3][0] += a.w * b.x; acc[3][1] += a.w * b.y; acc[3][2] += a.w * b.z; acc[3][3] += a.w * b.w;
        }
    }

    // epilogue: per-row min of y2[m] - 2*acc, packed with index
    float y2r[4];
    int   mr[4];
    #pragma unroll
    for (int j = 0; j < 4; j++) {
        int m = m0 + tx * 4 + j;
        mr[j] = m;
        y2r[j] = (m < M_LIB) ? g_y2[m] : __int_as_float(0x7F800000); // +inf
    }
    #pragma unroll
    for (int i = 0; i < 4; i++) {
        unsigned long long p = 0xFFFFFFFFFFFFFFFFull;
        #pragma unroll
        for (int j = 0; j < 4; j++) {
            float sc = fmaf(-2.f, acc[i][j], y2r[j]);
            unsigned long long pk = ((unsigned long long)fenc(sc) << 32) | (unsigned int)mr[j];
            p = min(p, pk);
        }
        sMin[ty * 4 + i][tx] = p;
    }
    __syncthreads();
    if (tid < 64) {
        unsigned long long p = 0xFFFFFFFFFFFFFFFFull;
        #pragma unroll
        for (int t = 0; t < 16; t++) p = min(p, sMin[tid][t]);
        int n = n0 + tid;
        if (n < N_PATCH) atomicMin(&g_min[n], p);
    }
}

// ---------------- reduce: min_val, argmax(min_val) -> s_idx, s_star, m_star ----------------
__global__ __launch_bounds__(1024) void k_reduce() {
    __shared__ unsigned long long sh[1024];
    int t = threadIdx.x;
    unsigned long long pk = 0ull;
    if (t < N_PATCH) {
        unsigned long long p = g_min[t];
        float score = fdec((unsigned int)(p >> 32));
        float d = sqrtf(fmaxf(g_x2[t] + score, 0.f));
        g_minval[t] = d;
        // pack for argmax with first-index tie-break: idx stored inverted
        pk = ((unsigned long long)fenc(d) << 32) | (unsigned int)(0xFFFFFFFFu - t);
    }
    sh[t] = pk;
    __syncthreads();
    for (int o = 512; o; o >>= 1) {
        if (t < o) sh[t] = max(sh[t], sh[t + o]);
        __syncthreads();
    }
    if (t == 0) {
        unsigned long long w = sh[0];
        int sidx = (int)(0xFFFFFFFFu - (unsigned int)(w & 0xFFFFFFFFu));
        g_sidx = sidx;
        g_s_star = fdec((unsigned int)(w >> 32));
        g_mstar = (int)(unsigned int)(g_min[sidx] & 0xFFFFFFFFu);
    }
}

// ---------------- w_dist: ||m_star - lib[m]|| for all m (warp per row) ----------------
__global__ void k_wdist(const float* __restrict__ B) {
    int warp = (blockIdx.x * blockDim.x + threadIdx.x) >> 5;
    int lane = threadIdx.x & 31;
    if (warp >= M_LIB) return;
    const float4* pm = (const float4*)(B + (size_t)g_mstar * DIMV);
    const float4* pb = (const float4*)(B + (size_t)warp * DIMV);
    float s = 0.f;
    #pragma unroll 3
    for (int i = lane; i < DIMV / 4; i += 32) {
        float4 a = pm[i], b = pb[i];
        float dx = a.x - b.x, dy = a.y - b.y, dz = a.z - b.z, dw = a.w - b.w;
        s += dx * dx + dy * dy + dz * dz + dw * dw;
    }
    #pragma unroll
    for (int o = 16; o; o >>= 1) s += __shfl_xor_sync(0xFFFFFFFFu, s, o);
    if (lane == 0) {
        float d = sqrtf(s);
        g_wpack[warp] = ((unsigned long long)fenc(d) << 32) | (unsigned int)warp;
    }
}

// ---------------- top-3 smallest w_dist + final scalar s ----------------
__global__ __launch_bounds__(1024) void k_top3_scalar(const float* __restrict__ A,
                                                      const float* __restrict__ B,
                                                      float* __restrict__ out) {
    __shared__ unsigned long long sh[1024];
    __shared__ int s_nn[3];
    __shared__ float s_dist[2];
    int t = threadIdx.x;

    int ex0 = -1, ex1 = -1;
    for (int pass = 0; pass < 3; pass++) {
        unsigned long long local = 0xFFFFFFFFFFFFFFFFull;
        for (int m = t; m < M_LIB; m += 1024) {
            unsigned long long p = g_wpack[m];
            int idx = (int)(unsigned int)(p & 0xFFFFFFFFu);
            if (idx != ex0 && idx != ex1) local = min(local, p);
        }
        sh[t] = local;
        __syncthreads();
        for (int o = 512; o; o >>= 1) {
            if (t < o) sh[t] = min(sh[t], sh[t + o]);
            __syncthreads();
        }
        int widx = (int)(unsigned int)(sh[0] & 0xFFFFFFFFu);
        if (t == 0) s_nn[pass] = widx;
        if (pass == 0) ex0 = widx; else if (pass == 1) ex1 = widx;
        __syncthreads();
    }

    // distances ||m_test - lib[nn1]||, ||m_test - lib[nn2]||  (warps 0 and 1)
    int warp = t >> 5, lane = t & 31;
    if (warp < 2) {
        int nn = s_nn[warp + 1];
        const float* a = A + (size_t)g_sidx * DIMV;
        const float* b = B + (size_t)nn * DIMV;
        float s = 0.f;
        for (int i = lane; i < DIMV; i += 32) {
            float df = a[i] - b[i];
            s += df * df;
        }
        #pragma unroll
        for (int o = 16; o; o >>= 1) s += __shfl_xor_sync(0xFFFFFFFFu, s, o);
        if (lane == 0) s_dist[warp] = sqrtf(s);
    }
    __syncthreads();
    if (t == 0) {
        float Ds = sqrtf((float)DIMV);
        float sstar = g_s_star;
        float w = 1.f - expf(sstar / Ds) / (expf(s_dist[0] / Ds) + expf(s_dist[1] / Ds));
        out[0] = w * sstar;
    }
}

// ---------------- bilinear upsample 26x26 -> 224x224 (half-pixel, clamp) ----------------
__global__ void k_upsample() {
    int oy = blockIdx.x;
    int ox = threadIdx.x;
    const float scale = (float)FMAP / (float)IMG;
    float sy = (oy + 0.5f) * scale - 0.5f;
    float sx = (ox + 0.5f) * scale - 0.5f;
    int y0 = (int)floorf(sy), x0 = (int)floorf(sx);
    float wy = sy - (float)y0, wx = sx - (float)x0;
    int y0c = min(max(y0, 0), FMAP - 1), y1c = min(max(y0 + 1, 0), FMAP - 1);
    int x0c = min(max(x0, 0), FMAP - 1), x1c = min(max(x0 + 1, 0), FMAP - 1);
    float v00 = g_minval[y0c * FMAP + x0c];
    float v01 = g_minval[y0c * FMAP + x1c];
    float v10 = g_minval[y1c * FMAP + x0c];
    float v11 = g_minval[y1c * FMAP + x1c];
    float top = v00 + (v01 - v00) * wx;
    float bot = v10 + (v11 - v10) * wx;
    g_up[oy * IMG + ox] = top + (bot - top) * wy;
}

__device__ __forceinline__ int reflect_idx(int i) {
    if (i < 0) i = -i;
    if (i > IMG - 1) i = 2 * (IMG - 1) - i;
    return i;
}

// horizontal blur (reflect), row per block
__global__ void k_blur_h() {
    __shared__ float row[IMG];
    int y = blockIdx.x, x = threadIdx.x;
    row[x] = g_up[y * IMG + x];
    __syncthreads();
    float s = 0.f;
    #pragma unroll
    for (int k = 0; k < KSIZE; k++) s += g_k1d[k] * row[reflect_idx(x + k - KHALF)];
    g_tmp[y * IMG + x] = s;
}

// vertical blur (reflect), row per block, coalesced column reads
__global__ void k_blur_v(float* __restrict__ out) {
    int y = blockIdx.x, x = threadIdx.x;
    float s = 0.f;
    #pragma unroll
    for (int k = 0; k < KSIZE; k++) s += g_k1d[k] * g_tmp[reflect_idx(y + k - KHALF) * IMG + x];
    out[y * IMG + x] = s;
}

// ---------------- launch ----------------
extern "C" void kernel_launch(void* const* d_in, const int* in_sizes, int n_in,
                              void* d_out, int out_size) {
    const float* patch = (const float*)d_in[0];  // [676, 384]
    const float* lib   = (const float*)d_in[1];  // [100000, 384]
    float* out = (float*)d_out;                  // [0]=s, [1..50176]=s_map

    float* x2p; cudaGetSymbolAddress((void**)&x2p, g_x2);
    float* y2p; cudaGetSymbolAddress((void**)&y2p, g_y2);

    k_init<<<1, 256>>>();
    k_sqnorm<<<(N_PATCH * 32 + 255) / 256, 256>>>(patch, x2p, N_PATCH);
    k_sqnorm<<<(M_LIB * 32 + 255) / 256, 256>>>(lib, y2p, M_LIB);

    dim3 grid((M_LIB + 63) / 64, (N_PATCH + 63) / 64);
    dim3 blk(16, 16);
    k_gemm_min<<<grid, blk>>>(patch, lib);

    k_reduce<<<1, 1024>>>();
    k_wdist<<<(M_LIB * 32 + 255) / 256, 256>>>(lib);
    k_top3_scalar<<<1, 1024>>>(patch, lib, out);

    k_upsample<<<IMG, IMG>>>();
    k_blur_h<<<IMG, IMG>>>();
    k_blur_v<<<IMG, IMG>>>(out + 1);
}

// round 3
// speedup vs baseline: 5.7472x; 5.7472x over previous
#include <cuda_runtime.h>
#include <cuda_bf16.h>
#include <math.h>
#include <stdint.h>

// ---------------- problem constants ----------------
#define N_PATCH 676          // 26*26
#define DIMV    384
#define M_LIB   100000
#define FMAP    26
#define IMG     224
#define KSIZE   33
#define KHALF   16

#define TILE_M  128          // lib rows per CTA
#define TILE_N  128          // patch rows per chunk
#define NCHUNK  6            // ceil(676/128)
#define NBLK    ((M_LIB + TILE_M - 1) / TILE_M)   // 782
#define KSTEPS  (DIMV / 16)  // 24

// smem tile pitch: 384 bf16 + 8 pad = 392 bf16 = 784 bytes (16B aligned, conflict-free ldmatrix)
#define PITCH_E 392
#define PITCH_B (PITCH_E * 2)

#define OFF_Y2     0                         // 128 floats
#define OFF_MINCOL 512                       // 128 u64
#define OFF_A      1536                      // lib tile  128*784 = 100352
#define OFF_B      (OFF_A + TILE_M * PITCH_B)
#define SMEM_GEMM  (OFF_B + TILE_N * PITCH_B)  // ~202 KB

// ---------------- device scratch ----------------
__device__ __align__(16) __nv_bfloat16 g_patchbf[N_PATCH * DIMV];
__device__ unsigned long long g_min[N_PATCH];
__device__ float              g_x2[N_PATCH];
__device__ float              g_y2[M_LIB];
__device__ float              g_minval[N_PATCH];
__device__ float              g_s_star;
__device__ int                g_sidx;
__device__ int                g_mstar;
__device__ unsigned long long g_wpack[M_LIB];
__device__ float              g_k1d[KSIZE];
__device__ float              g_up[IMG * IMG];
__device__ float              g_tmp[IMG * IMG];

// ---------------- helpers ----------------
__device__ __forceinline__ unsigned int fenc(float f) {
    unsigned int u = __float_as_uint(f);
    return (u & 0x80000000u) ? ~u : (u | 0x80000000u);
}
__device__ __forceinline__ float fdec(unsigned int k) {
    unsigned int u = (k & 0x80000000u) ? (k ^ 0x80000000u) : ~k;
    return __uint_as_float(u);
}
__device__ __forceinline__ uint32_t smem_u32(const void* p) {
    uint32_t a;
    asm("{ .reg .u64 t; cvta.to.shared.u64 t, %1; cvt.u32.u64 %0, t; }" : "=r"(a) : "l"(p));
    return a;
}
__device__ __forceinline__ void ldsm4(uint32_t a, uint32_t& r0, uint32_t& r1, uint32_t& r2, uint32_t& r3) {
    asm volatile("ldmatrix.sync.aligned.m8n8.x4.shared.b16 {%0,%1,%2,%3}, [%4];"
                 : "=r"(r0), "=r"(r1), "=r"(r2), "=r"(r3) : "r"(a));
}
__device__ __forceinline__ void mma16816(float* c, uint32_t a0, uint32_t a1, uint32_t a2, uint32_t a3,
                                         uint32_t b0, uint32_t b1) {
    asm volatile("mma.sync.aligned.m16n8k16.row.col.f32.bf16.bf16.f32 "
                 "{%0,%1,%2,%3}, {%4,%5,%6,%7}, {%8,%9}, {%0,%1,%2,%3};"
                 : "+f"(c[0]), "+f"(c[1]), "+f"(c[2]), "+f"(c[3])
                 : "r"(a0), "r"(a1), "r"(a2), "r"(a3), "r"(b0), "r"(b1));
}

// ---------------- init ----------------
__global__ void k_init() {
    int t = threadIdx.x;
    for (int i = t; i < N_PATCH; i += blockDim.x) g_min[i] = 0xFFFFFFFFFFFFFFFFull;
    if (t == 0) {
        double k[KSIZE]; double s = 0.0;
        for (int i = 0; i < KSIZE; i++) {
            double x = (double)i - (KSIZE - 1) / 2.0;
            k[i] = exp(-0.5 * (x / 4.0) * (x / 4.0));
            s += k[i];
        }
        for (int i = 0; i < KSIZE; i++) g_k1d[i] = (float)(k[i] / s);
    }
}

// ---------------- squared norms (warp per row) ----------------
__global__ void k_sqnorm(const float* __restrict__ x, float* __restrict__ out, int rows) {
    int warp = (blockIdx.x * blockDim.x + threadIdx.x) >> 5;
    int lane = threadIdx.x & 31;
    if (warp >= rows) return;
    const float4* p = (const float4*)(x + (size_t)warp * DIMV);
    float s = 0.f;
    #pragma unroll 3
    for (int i = lane; i < DIMV / 4; i += 32) {
        float4 v = p[i];
        s += v.x * v.x + v.y * v.y + v.z * v.z + v.w * v.w;
    }
    #pragma unroll
    for (int o = 16; o; o >>= 1) s += __shfl_xor_sync(0xFFFFFFFFu, s, o);
    if (lane == 0) out[warp] = s;
}

// ---------------- patch: fp32 -> bf16 + norms ----------------
__global__ void k_convert(const float* __restrict__ src, __nv_bfloat16* __restrict__ dst,
                          float* __restrict__ norms, int rows) {
    int warp = (blockIdx.x * blockDim.x + threadIdx.x) >> 5;
    int lane = threadIdx.x & 31;
    if (warp >= rows) return;
    const float4* p = (const float4*)(src + (size_t)warp * DIMV);
    __nv_bfloat162* q = (__nv_bfloat162*)(dst + (size_t)warp * DIMV);
    float s = 0.f;
    #pragma unroll 3
    for (int i = lane; i < DIMV / 4; i += 32) {
        float4 v = p[i];
        s += v.x * v.x + v.y * v.y + v.z * v.z + v.w * v.w;
        q[i * 2]     = __floats2bfloat162_rn(v.x, v.y);
        q[i * 2 + 1] = __floats2bfloat162_rn(v.z, v.w);
    }
    #pragma unroll
    for (int o = 16; o; o >>= 1) s += __shfl_xor_sync(0xFFFFFFFFu, s, o);
    if (lane == 0) norms[warp] = s;
}

// ---------------- bf16 HMMA GEMM + per-patch min ----------------
// CTA b owns lib rows [b*128, b*128+128). D[m][n] = dot(lib_m, patch_n).
// score(n,m) = y2[m] - 2*D -> min over m (packed with index).
__global__ __launch_bounds__(256, 1) void k_gemm_bf16(const float* __restrict__ lib) {
    extern __shared__ char smem[];
    const uint32_t sb = smem_u32(smem);
    const int tid  = threadIdx.x;
    const int wid  = tid >> 5;
    const int lane = tid & 31;
    const int m0   = blockIdx.x * TILE_M;
    const int wm   = wid & 3;        // 4 warps in M (32 rows each)
    const int wn   = wid >> 2;       // 2 warps in N (64 cols each)

    // y2 tile (+inf for invalid rows)
    if (tid < TILE_M) {
        int m = m0 + tid;
        *(float*)(smem + OFF_Y2 + tid * 4) = (m < M_LIB) ? g_y2[m] : __int_as_float(0x7F800000);
    }

    // load lib tile [128 x 384] fp32 -> bf16 into smem (pitch 784B)
    {
        #pragma unroll
        for (int it = 0; it < 48; it++) {
            int idx = it * 256 + tid;
            int r = idx / 96, c4 = (idx % 96) * 4;
            int m = m0 + r;
            float4 v = make_float4(0.f, 0.f, 0.f, 0.f);
            if (m < M_LIB) v = *(const float4*)(lib + (size_t)m * DIMV + c4);
            uint32_t lo = __float_as_uint(0.f), hi = lo;
            __nv_bfloat162 b0 = __floats2bfloat162_rn(v.x, v.y);
            __nv_bfloat162 b1 = __floats2bfloat162_rn(v.z, v.w);
            lo = *(uint32_t*)&b0; hi = *(uint32_t*)&b1;
            *(uint2*)(smem + OFF_A + r * PITCH_B + c4 * 2) = make_uint2(lo, hi);
        }
    }

    // ldmatrix base addresses
    const uint32_t aRow = lane & 15, aSel = lane >> 4;
    uint32_t aBase[2];
    #pragma unroll
    for (int mt = 0; mt < 2; mt++)
        aBase[mt] = sb + OFF_A + (wm * 32 + mt * 16 + aRow) * PITCH_B + aSel * 16;
    const uint32_t bRow = (lane & 7) + ((lane >> 4) << 3);
    const uint32_t bSel = (lane >> 3) & 1;
    uint32_t bBase[4];
    #pragma unroll
    for (int t = 0; t < 4; t++)
        bBase[t] = sb + OFF_B + (wn * 64 + t * 16 + bRow) * PITCH_B + bSel * 16;

    const int g  = lane >> 2;        // row group 0..7
    const int c2 = (lane & 3) * 2;   // col pair

    for (int nc = 0; nc < NCHUNK; nc++) {
        const int n0 = nc * TILE_N;
        __syncthreads();  // prior epilogue/flush done before overwriting mincol/B
        if (tid < TILE_N) *(unsigned long long*)(smem + OFF_MINCOL + tid * 8) = 0xFFFFFFFFFFFFFFFFull;
        // load patch chunk [128 x 384] bf16
        {
            const uint4* srcb = (const uint4*)g_patchbf;
            #pragma unroll
            for (int it = 0; it < 24; it++) {
                int idx = it * 256 + tid;
                int r = idx / 48, c8 = (idx % 48) * 8;
                int n = n0 + r;
                uint4 v = make_uint4(0u, 0u, 0u, 0u);
                if (n < N_PATCH) v = srcb[((size_t)n * DIMV + c8) >> 3];
                *(uint4*)(smem + OFF_B + r * PITCH_B + c8 * 2) = v;
            }
        }
        __syncthreads();

        // MMA mainloop: warp tile 32(M) x 64(N)
        float acc[2][8][4];
        #pragma unroll
        for (int mt = 0; mt < 2; mt++)
            #pragma unroll
            for (int t = 0; t < 8; t++)
                #pragma unroll
                for (int e = 0; e < 4; e++) acc[mt][t][e] = 0.f;

        for (int k = 0; k < KSTEPS; k++) {
            const uint32_t koff = k * 32;
            uint32_t a[2][4];
            #pragma unroll
            for (int mt = 0; mt < 2; mt++)
                ldsm4(aBase[mt] + koff, a[mt][0], a[mt][1], a[mt][2], a[mt][3]);
            uint32_t b[4][4];
            #pragma unroll
            for (int t = 0; t < 4; t++)
                ldsm4(bBase[t] + koff, b[t][0], b[t][1], b[t][2], b[t][3]);
            #pragma unroll
            for (int mt = 0; mt < 2; mt++)
                #pragma unroll
                for (int t = 0; t < 4; t++) {
                    mma16816(acc[mt][t * 2],     a[mt][0], a[mt][1], a[mt][2], a[mt][3], b[t][0], b[t][1]);
                    mma16816(acc[mt][t * 2 + 1], a[mt][0], a[mt][1], a[mt][2], a[mt][3], b[t][2], b[t][3]);
                }
        }

        // epilogue: score = y2[m] - 2*acc, per-column packed min
        float y2r[2][2];
        unsigned int mrow[2][2];
        #pragma unroll
        for (int mt = 0; mt < 2; mt++) {
            int ml = wm * 32 + mt * 16 + g;
            y2r[mt][0] = *(const float*)(smem + OFF_Y2 + ml * 4);
            y2r[mt][1] = *(const float*)(smem + OFF_Y2 + (ml + 8) * 4);
            mrow[mt][0] = (unsigned int)(m0 + ml);
            mrow[mt][1] = (unsigned int)(m0 + ml + 8);
        }
        #pragma unroll
        for (int t = 0; t < 8; t++) {
            #pragma unroll
            for (int j = 0; j < 2; j++) {
                unsigned long long p = 0xFFFFFFFFFFFFFFFFull;
                #pragma unroll
                for (int mt = 0; mt < 2; mt++) {
                    float v0 = fmaf(-2.f, acc[mt][t][j],     y2r[mt][0]);
                    float v1 = fmaf(-2.f, acc[mt][t][j + 2], y2r[mt][1]);
                    unsigned long long p0 = ((unsigned long long)fenc(v0) << 32) | mrow[mt][0];
                    unsigned long long p1 = ((unsigned long long)fenc(v1) << 32) | mrow[mt][1];
                    p = min(p, min(p0, p1));
                }
                #pragma unroll
                for (int o = 4; o <= 16; o <<= 1)
                    p = min(p, __shfl_xor_sync(0xFFFFFFFFu, p, o));
                if (lane < 4) {
                    int nb = wn * 64 + t * 8 + c2 + j;
                    atomicMin((unsigned long long*)(smem + OFF_MINCOL + nb * 8), p);
                }
            }
        }
        __syncthreads();
        if (tid < TILE_N) {
            int n = n0 + tid;
            if (n < N_PATCH)
                atomicMin(&g_min[n], *(unsigned long long*)(smem + OFF_MINCOL + tid * 8));
        }
    }
}

// ---------------- reduce: min_val, argmax -> s_idx, s_star, m_star ----------------
__global__ __launch_bounds__(1024) void k_reduce() {
    __shared__ unsigned long long sh[1024];
    int t = threadIdx.x;
    unsigned long long pk = 0ull;
    if (t < N_PATCH) {
        unsigned long long p = g_min[t];
        float score = fdec((unsigned int)(p >> 32));
        float d = sqrtf(fmaxf(g_x2[t] + score, 0.f));
        g_minval[t] = d;
        pk = ((unsigned long long)fenc(d) << 32) | (unsigned int)(0xFFFFFFFFu - t);
    }
    sh[t] = pk;
    __syncthreads();
    for (int o = 512; o; o >>= 1) {
        if (t < o) sh[t] = max(sh[t], sh[t + o]);
        __syncthreads();
    }
    if (t == 0) {
        unsigned long long w = sh[0];
        int sidx = (int)(0xFFFFFFFFu - (unsigned int)(w & 0xFFFFFFFFu));
        g_sidx = sidx;
        g_s_star = fdec((unsigned int)(w >> 32));
        g_mstar = (int)(unsigned int)(g_min[sidx] & 0xFFFFFFFFu);
    }
}

// ---------------- w_dist (warp per row, fp32 exact) ----------------
__global__ void k_wdist(const float* __restrict__ B) {
    int warp = (blockIdx.x * blockDim.x + threadIdx.x) >> 5;
    int lane = threadIdx.x & 31;
    if (warp >= M_LIB) return;
    const float4* pm = (const float4*)(B + (size_t)g_mstar * DIMV);
    const float4* pb = (const float4*)(B + (size_t)warp * DIMV);
    float s = 0.f;
    #pragma unroll 3
    for (int i = lane; i < DIMV / 4; i += 32) {
        float4 a = pm[i], b = pb[i];
        float dx = a.x - b.x, dy = a.y - b.y, dz = a.z - b.z, dw = a.w - b.w;
        s += dx * dx + dy * dy + dz * dz + dw * dw;
    }
    #pragma unroll
    for (int o = 16; o; o >>= 1) s += __shfl_xor_sync(0xFFFFFFFFu, s, o);
    if (lane == 0) {
        float d = sqrtf(s);
        g_wpack[warp] = ((unsigned long long)fenc(d) << 32) | (unsigned int)warp;
    }
}

// ---------------- top-3 + final scalar ----------------
__global__ __launch_bounds__(1024) void k_top3_scalar(const float* __restrict__ A,
                                                      const float* __restrict__ B,
                                                      float* __restrict__ out) {
    __shared__ unsigned long long sh[1024];
    __shared__ int s_nn[3];
    __shared__ float s_dist[2];
    int t = threadIdx.x;

    int ex0 = -1, ex1 = -1;
    for (int pass = 0; pass < 3; pass++) {
        unsigned long long local = 0xFFFFFFFFFFFFFFFFull;
        for (int m = t; m < M_LIB; m += 1024) {
            unsigned long long p = g_wpack[m];
            int idx = (int)(unsigned int)(p & 0xFFFFFFFFu);
            if (idx != ex0 && idx != ex1) local = min(local, p);
        }
        sh[t] = local;
        __syncthreads();
        for (int o = 512; o; o >>= 1) {
            if (t < o) sh[t] = min(sh[t], sh[t + o]);
            __syncthreads();
        }
        int widx = (int)(unsigned int)(sh[0] & 0xFFFFFFFFu);
        if (t == 0) s_nn[pass] = widx;
        if (pass == 0) ex0 = widx; else if (pass == 1) ex1 = widx;
        __syncthreads();
    }

    int warp = t >> 5, lane = t & 31;
    if (warp < 2) {
        int nn = s_nn[warp + 1];
        const float* a = A + (size_t)g_sidx * DIMV;
        const float* b = B + (size_t)nn * DIMV;
        float s = 0.f;
        for (int i = lane; i < DIMV; i += 32) {
            float df = a[i] - b[i];
            s += df * df;
        }
        #pragma unroll
        for (int o = 16; o; o >>= 1) s += __shfl_xor_sync(0xFFFFFFFFu, s, o);
        if (lane == 0) s_dist[warp] = sqrtf(s);
    }
    __syncthreads();
    if (t == 0) {
        float Ds = sqrtf((float)DIMV);
        float sstar = g_s_star;
        float w = 1.f - expf(sstar / Ds) / (expf(s_dist[0] / Ds) + expf(s_dist[1] / Ds));
        out[0] = w * sstar;
    }
}

// ---------------- bilinear upsample 26x26 -> 224x224 ----------------
__global__ void k_upsample() {
    int oy = blockIdx.x;
    int ox = threadIdx.x;
    const float scale = (float)FMAP / (float)IMG;
    float sy = (oy + 0.5f) * scale - 0.5f;
    float sx = (ox + 0.5f) * scale - 0.5f;
    int y0 = (int)floorf(sy), x0 = (int)floorf(sx);
    float wy = sy - (float)y0, wx = sx - (float)x0;
    int y0c = min(max(y0, 0), FMAP - 1), y1c = min(max(y0 + 1, 0), FMAP - 1);
    int x0c = min(max(x0, 0), FMAP - 1), x1c = min(max(x0 + 1, 0), FMAP - 1);
    float v00 = g_minval[y0c * FMAP + x0c];
    float v01 = g_minval[y0c * FMAP + x1c];
    float v10 = g_minval[y1c * FMAP + x0c];
    float v11 = g_minval[y1c * FMAP + x1c];
    float top = v00 + (v01 - v00) * wx;
    float bot = v10 + (v11 - v10) * wx;
    g_up[oy * IMG + ox] = top + (bot - top) * wy;
}

__device__ __forceinline__ int reflect_idx(int i) {
    if (i < 0) i = -i;
    if (i > IMG - 1) i = 2 * (IMG - 1) - i;
    return i;
}

__global__ void k_blur_h() {
    __shared__ float row[IMG];
    int y = blockIdx.x, x = threadIdx.x;
    row[x] = g_up[y * IMG + x];
    __syncthreads();
    float s = 0.f;
    #pragma unroll
    for (int k = 0; k < KSIZE; k++) s += g_k1d[k] * row[reflect_idx(x + k - KHALF)];
    g_tmp[y * IMG + x] = s;
}

__global__ void k_blur_v(float* __restrict__ out) {
    int y = blockIdx.x, x = threadIdx.x;
    float s = 0.f;
    #pragma unroll
    for (int k = 0; k < KSIZE; k++) s += g_k1d[k] * g_tmp[reflect_idx(y + k - KHALF) * IMG + x];
    out[y * IMG + x] = s;
}

// ---------------- launch ----------------
extern "C" void kernel_launch(void* const* d_in, const int* in_sizes, int n_in,
                              void* d_out, int out_size) {
    const float* patch = (const float*)d_in[0];  // [676, 384]
    const float* lib   = (const float*)d_in[1];  // [100000, 384]
    float* out = (float*)d_out;                  // [0]=s, [1..50176]=s_map

    float* x2p; cudaGetSymbolAddress((void**)&x2p, g_x2);
    float* y2p; cudaGetSymbolAddress((void**)&y2p, g_y2);
    __nv_bfloat16* patchbf; cudaGetSymbolAddress((void**)&patchbf, g_patchbf);

    static int smem_set = 0;
    if (!smem_set) {
        cudaFuncSetAttribute(k_gemm_bf16, cudaFuncAttributeMaxDynamicSharedMemorySize, SMEM_GEMM);
        smem_set = 1;
    }

    k_init<<<1, 256>>>();
    k_sqnorm<<<(M_LIB * 32 + 255) / 256, 256>>>(lib, y2p, M_LIB);
    k_convert<<<(N_PATCH * 32 + 255) / 256, 256>>>(patch, patchbf, x2p, N_PATCH);

    k_gemm_bf16<<<NBLK, 256, SMEM_GEMM>>>(lib);

    k_reduce<<<1, 1024>>>();
    k_wdist<<<(M_LIB * 32 + 255) / 256, 256>>>(lib);
    k_top3_scalar<<<1, 1024>>>(patch, lib, out);

    k_upsample<<<IMG, IMG>>>();
    k_blur_h<<<IMG, IMG>>>();
    k_blur_v<<<IMG, IMG>>>(out + 1);
}

// round 4
// speedup vs baseline: 6.3553x; 1.1058x over previous
#include <cuda_runtime.h>
#include <cuda_bf16.h>
#include <math.h>
#include <stdint.h>

// ---------------- problem constants ----------------
#define N_PATCH 676          // 26*26
#define DIMV    384
#define M_LIB   100000
#define FMAP    26
#define IMG     224
#define KSIZE   33
#define KHALF   16

#define TILE_M  128          // lib rows per CTA
#define TILE_N  128          // patch rows per chunk
#define NCHUNK  6            // ceil(676/128)
#define NBLK    ((M_LIB + TILE_M - 1) / TILE_M)   // 782
#define KSTEPS  (DIMV / 16)  // 24
#define NTHREADS 512

// smem tile pitch: 384 bf16 + 8 pad = 392 bf16 = 784 bytes (16B aligned, conflict-free ldmatrix)
#define PITCH_E 392
#define PITCH_B (PITCH_E * 2)

#define OFF_Y2     0                         // 128 floats
#define OFF_MINCOL 512                       // 128 u64
#define OFF_A      1536                      // lib tile  128*784 = 100352
#define OFF_B      (OFF_A + TILE_M * PITCH_B)
#define SMEM_GEMM  (OFF_B + TILE_N * PITCH_B)  // ~202 KB

// ---------------- device scratch ----------------
__device__ __align__(16) __nv_bfloat16 g_patchbf[N_PATCH * DIMV];
__device__ unsigned long long g_min[N_PATCH];
__device__ float              g_x2[N_PATCH];
__device__ float              g_y2[M_LIB];
__device__ float              g_minval[N_PATCH];
__device__ float              g_s_star;
__device__ int                g_sidx;
__device__ int                g_mstar;
__device__ unsigned long long g_wpack[M_LIB];
__device__ float              g_k1d[KSIZE];
__device__ float              g_up[IMG * IMG];
__device__ float              g_tmp[IMG * IMG];

// ---------------- helpers ----------------
__device__ __forceinline__ unsigned int fenc(float f) {
    unsigned int u = __float_as_uint(f);
    return (u & 0x80000000u) ? ~u : (u | 0x80000000u);
}
__device__ __forceinline__ float fdec(unsigned int k) {
    unsigned int u = (k & 0x80000000u) ? (k ^ 0x80000000u) : ~k;
    return __uint_as_float(u);
}
__device__ __forceinline__ uint32_t smem_u32(const void* p) {
    uint32_t a;
    asm("{ .reg .u64 t; cvta.to.shared.u64 t, %1; cvt.u32.u64 %0, t; }" : "=r"(a) : "l"(p));
    return a;
}
__device__ __forceinline__ void ldsm4(uint32_t a, uint32_t& r0, uint32_t& r1, uint32_t& r2, uint32_t& r3) {
    asm volatile("ldmatrix.sync.aligned.m8n8.x4.shared.b16 {%0,%1,%2,%3}, [%4];"
                 : "=r"(r0), "=r"(r1), "=r"(r2), "=r"(r3) : "r"(a));
}
__device__ __forceinline__ void mma16816(float* c, uint32_t a0, uint32_t a1, uint32_t a2, uint32_t a3,
                                         uint32_t b0, uint32_t b1) {
    asm volatile("mma.sync.aligned.m16n8k16.row.col.f32.bf16.bf16.f32 "
                 "{%0,%1,%2,%3}, {%4,%5,%6,%7}, {%8,%9}, {%0,%1,%2,%3};"
                 : "+f"(c[0]), "+f"(c[1]), "+f"(c[2]), "+f"(c[3])
                 : "r"(a0), "r"(a1), "r"(a2), "r"(a3), "r"(b0), "r"(b1));
}

// ---------------- init ----------------
__global__ void k_init() {
    int t = threadIdx.x;
    for (int i = t; i < N_PATCH; i += blockDim.x) g_min[i] = 0xFFFFFFFFFFFFFFFFull;
    if (t == 0) {
        double k[KSIZE]; double s = 0.0;
        for (int i = 0; i < KSIZE; i++) {
            double x = (double)i - (KSIZE - 1) / 2.0;
            k[i] = exp(-0.5 * (x / 4.0) * (x / 4.0));
            s += k[i];
        }
        for (int i = 0; i < KSIZE; i++) g_k1d[i] = (float)(k[i] / s);
    }
}

// ---------------- squared norms (warp per row) ----------------
__global__ void k_sqnorm(const float* __restrict__ x, float* __restrict__ out, int rows) {
    int warp = (blockIdx.x * blockDim.x + threadIdx.x) >> 5;
    int lane = threadIdx.x & 31;
    if (warp >= rows) return;
    const float4* p = (const float4*)(x + (size_t)warp * DIMV);
    float s = 0.f;
    #pragma unroll 3
    for (int i = lane; i < DIMV / 4; i += 32) {
        float4 v = p[i];
        s += v.x * v.x + v.y * v.y + v.z * v.z + v.w * v.w;
    }
    #pragma unroll
    for (int o = 16; o; o >>= 1) s += __shfl_xor_sync(0xFFFFFFFFu, s, o);
    if (lane == 0) out[warp] = s;
}

// ---------------- patch: fp32 -> bf16 + norms ----------------
__global__ void k_convert(const float* __restrict__ src, __nv_bfloat16* __restrict__ dst,
                          float* __restrict__ norms, int rows) {
    int warp = (blockIdx.x * blockDim.x + threadIdx.x) >> 5;
    int lane = threadIdx.x & 31;
    if (warp >= rows) return;
    const float4* p = (const float4*)(src + (size_t)warp * DIMV);
    __nv_bfloat162* q = (__nv_bfloat162*)(dst + (size_t)warp * DIMV);
    float s = 0.f;
    #pragma unroll 3
    for (int i = lane; i < DIMV / 4; i += 32) {
        float4 v = p[i];
        s += v.x * v.x + v.y * v.y + v.z * v.z + v.w * v.w;
        q[i * 2]     = __floats2bfloat162_rn(v.x, v.y);
        q[i * 2 + 1] = __floats2bfloat162_rn(v.z, v.w);
    }
    #pragma unroll
    for (int o = 16; o; o >>= 1) s += __shfl_xor_sync(0xFFFFFFFFu, s, o);
    if (lane == 0) norms[warp] = s;
}

// ---------------- bf16 HMMA GEMM + per-patch min ----------------
// 512 threads, 16 warps, warp tile 32(M) x 32(N).
// CTA b owns lib rows [b*128, b*128+128). score(n,m) = y2[m] - 2*dot -> packed min over m.
__global__ __launch_bounds__(NTHREADS, 1) void k_gemm_bf16(const float* __restrict__ lib) {
    extern __shared__ char smem[];
    const uint32_t sb = smem_u32(smem);
    const int tid  = threadIdx.x;
    const int wid  = tid >> 5;
    const int lane = tid & 31;
    const int m0   = blockIdx.x * TILE_M;
    const int wm   = wid & 3;        // 4 warps in M (32 rows each)
    const int wn   = wid >> 2;       // 4 warps in N (32 cols each)

    // y2 tile (+inf for invalid rows)
    if (tid < TILE_M) {
        int m = m0 + tid;
        *(float*)(smem + OFF_Y2 + tid * 4) = (m < M_LIB) ? g_y2[m] : __int_as_float(0x7F800000);
    }

    // load lib tile [128 x 384] fp32 -> bf16 into smem (pitch 784B)
    {
        #pragma unroll
        for (int it = 0; it < 24; it++) {
            int idx = it * NTHREADS + tid;
            int r = idx / 96, c4 = (idx % 96) * 4;
            int m = m0 + r;
            float4 v = make_float4(0.f, 0.f, 0.f, 0.f);
            if (m < M_LIB) v = *(const float4*)(lib + (size_t)m * DIMV + c4);
            __nv_bfloat162 b0 = __floats2bfloat162_rn(v.x, v.y);
            __nv_bfloat162 b1 = __floats2bfloat162_rn(v.z, v.w);
            *(uint2*)(smem + OFF_A + r * PITCH_B + c4 * 2) = make_uint2(*(uint32_t*)&b0, *(uint32_t*)&b1);
        }
    }

    // ldmatrix base addresses
    const uint32_t aRow = lane & 15, aSel = lane >> 4;
    uint32_t aBase[2];
    #pragma unroll
    for (int mt = 0; mt < 2; mt++)
        aBase[mt] = sb + OFF_A + (wm * 32 + mt * 16 + aRow) * PITCH_B + aSel * 16;
    const uint32_t bRow = (lane & 7) + ((lane >> 4) << 3);
    const uint32_t bSel = (lane >> 3) & 1;
    uint32_t bBase[2];
    #pragma unroll
    for (int t = 0; t < 2; t++)
        bBase[t] = sb + OFF_B + (wn * 32 + t * 16 + bRow) * PITCH_B + bSel * 16;

    const int g  = lane >> 2;        // row group 0..7
    const int c2 = (lane & 3) * 2;   // col pair

    for (int nc = 0; nc < NCHUNK; nc++) {
        const int n0 = nc * TILE_N;
        __syncthreads();  // prior epilogue done before overwriting mincol/B
        if (tid < TILE_N) *(unsigned long long*)(smem + OFF_MINCOL + tid * 8) = 0xFFFFFFFFFFFFFFFFull;
        // load patch chunk [128 x 384] bf16
        {
            const uint4* srcb = (const uint4*)g_patchbf;
            #pragma unroll
            for (int it = 0; it < 12; it++) {
                int idx = it * NTHREADS + tid;
                int r = idx / 48, c8 = (idx % 48) * 8;
                int n = n0 + r;
                uint4 v = make_uint4(0u, 0u, 0u, 0u);
                if (n < N_PATCH) v = srcb[((size_t)n * DIMV + c8) >> 3];
                *(uint4*)(smem + OFF_B + r * PITCH_B + c8 * 2) = v;
            }
        }
        __syncthreads();

        // MMA mainloop: warp tile 32(M) x 32(N)
        float acc[2][4][4];
        #pragma unroll
        for (int mt = 0; mt < 2; mt++)
            #pragma unroll
            for (int t = 0; t < 4; t++)
                #pragma unroll
                for (int e = 0; e < 4; e++) acc[mt][t][e] = 0.f;

        #pragma unroll 4
        for (int k = 0; k < KSTEPS; k++) {
            const uint32_t koff = k * 32;
            uint32_t a[2][4];
            #pragma unroll
            for (int mt = 0; mt < 2; mt++)
                ldsm4(aBase[mt] + koff, a[mt][0], a[mt][1], a[mt][2], a[mt][3]);
            uint32_t b[2][4];
            #pragma unroll
            for (int t = 0; t < 2; t++)
                ldsm4(bBase[t] + koff, b[t][0], b[t][1], b[t][2], b[t][3]);
            #pragma unroll
            for (int mt = 0; mt < 2; mt++)
                #pragma unroll
                for (int t = 0; t < 2; t++) {
                    mma16816(acc[mt][t * 2],     a[mt][0], a[mt][1], a[mt][2], a[mt][3], b[t][0], b[t][1]);
                    mma16816(acc[mt][t * 2 + 1], a[mt][0], a[mt][1], a[mt][2], a[mt][3], b[t][2], b[t][3]);
                }
        }

        // epilogue: score = y2[m] - 2*acc, per-column packed min
        float y2r[2][2];
        unsigned int mrow[2][2];
        #pragma unroll
        for (int mt = 0; mt < 2; mt++) {
            int ml = wm * 32 + mt * 16 + g;
            y2r[mt][0] = *(const float*)(smem + OFF_Y2 + ml * 4);
            y2r[mt][1] = *(const float*)(smem + OFF_Y2 + (ml + 8) * 4);
            mrow[mt][0] = (unsigned int)(m0 + ml);
            mrow[mt][1] = (unsigned int)(m0 + ml + 8);
        }
        #pragma unroll
        for (int t = 0; t < 4; t++) {
            #pragma unroll
            for (int j = 0; j < 2; j++) {
                unsigned long long p = 0xFFFFFFFFFFFFFFFFull;
                #pragma unroll
                for (int mt = 0; mt < 2; mt++) {
                    float v0 = fmaf(-2.f, acc[mt][t][j],     y2r[mt][0]);
                    float v1 = fmaf(-2.f, acc[mt][t][j + 2], y2r[mt][1]);
                    unsigned long long p0 = ((unsigned long long)fenc(v0) << 32) | mrow[mt][0];
                    unsigned long long p1 = ((unsigned long long)fenc(v1) << 32) | mrow[mt][1];
                    p = min(p, min(p0, p1));
                }
                #pragma unroll
                for (int o = 4; o <= 16; o <<= 1)
                    p = min(p, __shfl_xor_sync(0xFFFFFFFFu, p, o));
                if (lane < 4) {
                    int nb = wn * 32 + t * 8 + c2 + j;
                    atomicMin((unsigned long long*)(smem + OFF_MINCOL + nb * 8), p);
                }
            }
        }
        __syncthreads();
        if (tid < TILE_N) {
            int n = n0 + tid;
            if (n < N_PATCH)
                atomicMin(&g_min[n], *(unsigned long long*)(smem + OFF_MINCOL + tid * 8));
        }
    }
}

// ---------------- reduce: min_val, argmax -> s_idx, s_star, m_star ----------------
__global__ __launch_bounds__(1024) void k_reduce() {
    __shared__ unsigned long long sh[1024];
    int t = threadIdx.x;
    unsigned long long pk = 0ull;
    if (t < N_PATCH) {
        unsigned long long p = g_min[t];
        float score = fdec((unsigned int)(p >> 32));
        float d = sqrtf(fmaxf(g_x2[t] + score, 0.f));
        g_minval[t] = d;
        pk = ((unsigned long long)fenc(d) << 32) | (unsigned int)(0xFFFFFFFFu - t);
    }
    sh[t] = pk;
    __syncthreads();
    for (int o = 512; o; o >>= 1) {
        if (t < o) sh[t] = max(sh[t], sh[t + o]);
        __syncthreads();
    }
    if (t == 0) {
        unsigned long long w = sh[0];
        int sidx = (int)(0xFFFFFFFFu - (unsigned int)(w & 0xFFFFFFFFu));
        g_sidx = sidx;
        g_s_star = fdec((unsigned int)(w >> 32));
        g_mstar = (int)(unsigned int)(g_min[sidx] & 0xFFFFFFFFu);
    }
}

// ---------------- w_dist (warp per row, fp32 exact) ----------------
__global__ void k_wdist(const float* __restrict__ B) {
    int warp = (blockIdx.x * blockDim.x + threadIdx.x) >> 5;
    int lane = threadIdx.x & 31;
    if (warp >= M_LIB) return;
    const float4* pm = (const float4*)(B + (size_t)g_mstar * DIMV);
    const float4* pb = (const float4*)(B + (size_t)warp * DIMV);
    float s = 0.f;
    #pragma unroll 3
    for (int i = lane; i < DIMV / 4; i += 32) {
        float4 a = pm[i], b = pb[i];
        float dx = a.x - b.x, dy = a.y - b.y, dz = a.z - b.z, dw = a.w - b.w;
        s += dx * dx + dy * dy + dz * dz + dw * dw;
    }
    #pragma unroll
    for (int o = 16; o; o >>= 1) s += __shfl_xor_sync(0xFFFFFFFFu, s, o);
    if (lane == 0) {
        float d = sqrtf(s);
        g_wpack[warp] = ((unsigned long long)fenc(d) << 32) | (unsigned int)warp;
    }
}

// ---------------- top-3 + final scalar ----------------
__global__ __launch_bounds__(1024) void k_top3_scalar(const float* __restrict__ A,
                                                      const float* __restrict__ B,
                                                      float* __restrict__ out) {
    __shared__ unsigned long long sh[1024];
    __shared__ int s_nn[3];
    __shared__ float s_dist[2];
    int t = threadIdx.x;

    int ex0 = -1, ex1 = -1;
    for (int pass = 0; pass < 3; pass++) {
        unsigned long long local = 0xFFFFFFFFFFFFFFFFull;
        for (int m = t; m < M_LIB; m += 1024) {
            unsigned long long p = g_wpack[m];
            int idx = (int)(unsigned int)(p & 0xFFFFFFFFu);
            if (idx != ex0 && idx != ex1) local = min(local, p);
        }
        sh[t] = local;
        __syncthreads();
        for (int o = 512; o; o >>= 1) {
            if (t < o) sh[t] = min(sh[t], sh[t + o]);
            __syncthreads();
        }
        int widx = (int)(unsigned int)(sh[0] & 0xFFFFFFFFu);
        if (t == 0) s_nn[pass] = widx;
        if (pass == 0) ex0 = widx; else if (pass == 1) ex1 = widx;
        __syncthreads();
    }

    int warp = t >> 5, lane = t & 31;
    if (warp < 2) {
        int nn = s_nn[warp + 1];
        const float* a = A + (size_t)g_sidx * DIMV;
        const float* b = B + (size_t)nn * DIMV;
        float s = 0.f;
        for (int i = lane; i < DIMV; i += 32) {
            float df = a[i] - b[i];
            s += df * df;
        }
        #pragma unroll
        for (int o = 16; o; o >>= 1) s += __shfl_xor_sync(0xFFFFFFFFu, s, o);
        if (lane == 0) s_dist[warp] = sqrtf(s);
    }
    __syncthreads();
    if (t == 0) {
        float Ds = sqrtf((float)DIMV);
        float sstar = g_s_star;
        float w = 1.f - expf(sstar / Ds) / (expf(s_dist[0] / Ds) + expf(s_dist[1] / Ds));
        out[0] = w * sstar;
    }
}

// ---------------- bilinear upsample 26x26 -> 224x224 ----------------
__global__ void k_upsample() {
    int oy = blockIdx.x;
    int ox = threadIdx.x;
    const float scale = (float)FMAP / (float)IMG;
    float sy = (oy + 0.5f) * scale - 0.5f;
    float sx = (ox + 0.5f) * scale - 0.5f;
    int y0 = (int)floorf(sy), x0 = (int)floorf(sx);
    float wy = sy - (float)y0, wx = sx - (float)x0;
    int y0c = min(max(y0, 0), FMAP - 1), y1c = min(max(y0 + 1, 0), FMAP - 1);
    int x0c = min(max(x0, 0), FMAP - 1), x1c = min(max(x0 + 1, 0), FMAP - 1);
    float v00 = g_minval[y0c * FMAP + x0c];
    float v01 = g_minval[y0c * FMAP + x1c];
    float v10 = g_minval[y1c * FMAP + x0c];
    float v11 = g_minval[y1c * FMAP + x1c];
    float top = v00 + (v01 - v00) * wx;
    float bot = v10 + (v11 - v10) * wx;
    g_up[oy * IMG + ox] = top + (bot - top) * wy;
}

__device__ __forceinline__ int reflect_idx(int i) {
    if (i < 0) i = -i;
    if (i > IMG - 1) i = 2 * (IMG - 1) - i;
    return i;
}

__global__ void k_blur_h() {
    __shared__ float row[IMG];
    int y = blockIdx.x, x = threadIdx.x;
    row[x] = g_up[y * IMG + x];
    __syncthreads();
    float s = 0.f;
    #pragma unroll
    for (int k = 0; k < KSIZE; k++) s += g_k1d[k] * row[reflect_idx(x + k - KHALF)];
    g_tmp[y * IMG + x] = s;
}

__global__ void k_blur_v(float* __restrict__ out) {
    int y = blockIdx.x, x = threadIdx.x;
    float s = 0.f;
    #pragma unroll
    for (int k = 0; k < KSIZE; k++) s += g_k1d[k] * g_tmp[reflect_idx(y + k - KHALF) * IMG + x];
    out[y * IMG + x] = s;
}

// ---------------- launch ----------------
extern "C" void kernel_launch(void* const* d_in, const int* in_sizes, int n_in,
                              void* d_out, int out_size) {
    const float* patch = (const float*)d_in[0];  // [676, 384]
    const float* lib   = (const float*)d_in[1];  // [100000, 384]
    float* out = (float*)d_out;                  // [0]=s, [1..50176]=s_map

    float* x2p; cudaGetSymbolAddress((void**)&x2p, g_x2);
    float* y2p; cudaGetSymbolAddress((void**)&y2p, g_y2);
    __nv_bfloat16* patchbf; cudaGetSymbolAddress((void**)&patchbf, g_patchbf);

    static int smem_set = 0;
    if (!smem_set) {
        cudaFuncSetAttribute(k_gemm_bf16, cudaFuncAttributeMaxDynamicSharedMemorySize, SMEM_GEMM);
        smem_set = 1;
    }

    k_init<<<1, 256>>>();
    k_sqnorm<<<(M_LIB * 32 + 255) / 256, 256>>>(lib, y2p, M_LIB);
    k_convert<<<(N_PATCH * 32 + 255) / 256, 256>>>(patch, patchbf, x2p, N_PATCH);

    k_gemm_bf16<<<NBLK, NTHREADS, SMEM_GEMM>>>(lib);

    k_reduce<<<1, 1024>>>();
    k_wdist<<<(M_LIB * 32 + 255) / 256, 256>>>(lib);
    k_top3_scalar<<<1, 1024>>>(patch, lib, out);

    k_upsample<<<IMG, IMG>>>();
    k_blur_h<<<IMG, IMG>>>();
    k_blur_v<<<IMG, IMG>>>(out + 1);
}